// round 15
// baseline (speedup 1.0000x reference)
#include <cuda_runtime.h>
#include <cuda_fp16.h>
#include <cstdint>
#include <cmath>
#include <cstring>
#include <algorithm>

// ---------------------------------------------------------------------------
// Problem constants
// ---------------------------------------------------------------------------
#define TT   480
#define PP   15
#define NSUB 32
#define TE   510
#define CC   256
#define BB   128
#define TPAD 512
#define KP   256           // k-pairs after padding K to 512
#define NCH  8             // K chunks of 64 (=32 pairs)
#define BM   128           // CTA M tile

// SMEM: A stages fp16 pair-packed: 128 rows x 128B, swizzle (row&7)<<4, x3
//       X stages fp16 pair-packed:  32 pair-rows x 512B, swizzle (p&3)<<5, x2
#define AS_BYTES 16384
#define XS_BYTES 16384
#define SMEM_BYTES (3 * AS_BYTES + 2 * XS_BYTES)   // 81920 -> 2 CTAs/SM

__device__ uint32_t g_A16[TPAD * KP];   // fp16 pair-packed operator (pad rows
                                        // 480..511 stay zero from module init)

// ---------------------------------------------------------------------------
// PTX helpers (sm_80-portable)
// ---------------------------------------------------------------------------
__device__ __forceinline__ uint32_t smem_u32(const void* p) {
    uint32_t a;
    asm("{ .reg .u64 t; cvta.to.shared.u64 t, %1; cvt.u32.u64 %0, t; }"
        : "=r"(a) : "l"(p));
    return a;
}
__device__ __forceinline__ void cp16(uint32_t dst, const void* src) {
    asm volatile("cp.async.cg.shared.global [%0], [%1], 16;" :: "r"(dst), "l"(src));
}
#define CP_COMMIT() asm volatile("cp.async.commit_group;" ::: "memory")
#define CP_WAIT(n)  asm volatile("cp.async.wait_group %0;" :: "n"(n) : "memory")

__device__ __forceinline__ void ldsm_x4(uint32_t* r, uint32_t addr) {
    asm volatile(
        "ldmatrix.sync.aligned.m8n8.x4.shared.b16 {%0,%1,%2,%3}, [%4];"
        : "=r"(r[0]), "=r"(r[1]), "=r"(r[2]), "=r"(r[3]) : "r"(addr));
}
__device__ __forceinline__ uint32_t lds32(uint32_t addr) {
    uint32_t v;
    asm volatile("ld.shared.b32 %0, [%1];" : "=r"(v) : "r"(addr));
    return v;
}
__device__ __forceinline__ void sts128(uint32_t addr, uint32_t w0, uint32_t w1,
                                       uint32_t w2, uint32_t w3) {
    asm volatile("st.shared.v4.b32 [%0], {%1,%2,%3,%4};"
                 :: "r"(addr), "r"(w0), "r"(w1), "r"(w2), "r"(w3) : "memory");
}
// pack two f32 -> f16x2 word; lo half = e (even k), hi half = o (odd k)
__device__ __forceinline__ uint32_t cvt_f16x2(float o, float e) {
    uint32_t w;
    asm("cvt.rn.f16x2.f32 %0, %1, %2;" : "=r"(w) : "f"(o), "f"(e));
    return w;
}

// fp16 MMA: D(f32) += A(f16) * B(f16), m16n8k16
__device__ __forceinline__ void mma_f16(float* d, const uint32_t* a,
                                        const uint32_t* b) {
    asm volatile(
        "mma.sync.aligned.m16n8k16.row.col.f32.f16.f16.f32 "
        "{%0,%1,%2,%3}, {%4,%5,%6,%7}, {%8,%9}, {%0,%1,%2,%3};"
        : "+f"(d[0]), "+f"(d[1]), "+f"(d[2]), "+f"(d[3])
        : "r"(a[0]), "r"(a[1]), "r"(a[2]), "r"(a[3]),
          "r"(b[0]), "r"(b[1]));
}

// ---------------------------------------------------------------------------
// Operator upload: read the HOST static h_A16 directly via ATS (GB300 is
// HMM-coherent; system memory LDG works without pinning) and store to g_A16.
// 480*256 words = 30720 uint4.
// ---------------------------------------------------------------------------
__global__ void __launch_bounds__(128) copyA_kernel(const uint4* __restrict__ src)
{
    const int i = blockIdx.x * 128 + threadIdx.x;
    ((uint4*)g_A16)[i] = src[i];
}

// ---------------------------------------------------------------------------
// GEMM: per CTA: batch b, 128 t-rows (A padded to 512), 128 channels.
// trend = A @ x ; out[0..N) = x - trend ; out[N..2N) = trend
// 128 threads = 4 warps in 2(M) x 2(N); warp tile 64x64; BK=64;
// A fp16 cp.async 3-stage (prefetch-2).
// X: fused LDG(fp32) -> cvt -> STS(fp16 pair-packed), 2-stage, staged in regs
//    quarter-chunk at a time (16 regs), interleaved with the MMA steps.
// ---------------------------------------------------------------------------
__global__ void __launch_bounds__(128, 2) stl_mma_kernel(
    const float* __restrict__ x, float* __restrict__ out)
{
    extern __shared__ __align__(16) char smem[];
    const uint32_t sb = smem_u32(smem);
    const uint32_t xbase = sb + 3 * AS_BYTES;

    const int tid = threadIdx.x;
    const int lane = tid & 31, wid = tid >> 5;
    const int warpM = wid & 1, warpN = wid >> 1;    // 2 x 2 warp grid
    const int t0 = blockIdx.x * BM;
    const int c0 = blockIdx.y * 128;
    const int b  = blockIdx.z;

    const uint32_t* gAr = g_A16 + (size_t)t0 * KP;         // [t][pair]
    const float*    gXr = x + (size_t)b * TT * CC + c0;    // [k][c] fp32

    auto issueA = [&](int kt) {
        const uint32_t aB = sb + (uint32_t)((kt % 3) * AS_BYTES);
        const int p0 = kt * 32;                 // pair offset
        const int r0 = tid >> 3;                // 0..15
        const uint32_t c16 = (uint32_t)(tid & 7) * 16;
#pragma unroll
        for (int i = 0; i < 8; i++) {
            const int r = r0 + i * 16;
            cp16(aB + (uint32_t)r * 128 + (c16 ^ (uint32_t)((r & 7) << 4)),
                 gAr + (size_t)r * KP + p0 + (tid & 7) * 4);
        }
        CP_COMMIT();
    };

    // X loader: quarter q (8 pair-rows) of chunk kt -> 2 units/thread.
    auto ldgX = [&](int kt, int q, float4* e, float4* o) {
#pragma unroll
        for (int u = 0; u < 2; u++) {
            const int id = tid + u * 128;
            const int p = kt * 32 + q * 8 + (id >> 5);     // global pair
            const int c = (id & 31) * 4;
            if (p < TT / 2) {
                e[u] = *(const float4*)(gXr + (size_t)(2 * p) * CC + c);
                o[u] = *(const float4*)(gXr + (size_t)(2 * p + 1) * CC + c);
            } else {
                e[u] = make_float4(0.f, 0.f, 0.f, 0.f);
                o[u] = make_float4(0.f, 0.f, 0.f, 0.f);
            }
        }
    };
    auto stsX = [&](int kt, int q, const float4* e, const float4* o) {
        const uint32_t xB = xbase + (uint32_t)((kt & 1) * XS_BYTES);
#pragma unroll
        for (int u = 0; u < 2; u++) {
            const int id = tid + u * 128;
            const int pl = q * 8 + (id >> 5);              // local pair row
            const uint32_t c16 = (uint32_t)(id & 31) * 16;
            const uint32_t addr = xB + (uint32_t)pl * 512 +
                                  (c16 ^ (uint32_t)((pl & 3) << 5));
            sts128(addr,
                   cvt_f16x2(o[u].x, e[u].x), cvt_f16x2(o[u].y, e[u].y),
                   cvt_f16x2(o[u].z, e[u].z), cvt_f16x2(o[u].w, e[u].w));
        }
    };

    float acc[4][8][4];
#pragma unroll
    for (int mi = 0; mi < 4; mi++)
#pragma unroll
        for (int nj = 0; nj < 8; nj++)
#pragma unroll
            for (int r = 0; r < 4; r++) acc[mi][nj][r] = 0.0f;

    const int lr = lane >> 2, lc = lane & 3;

    // ldmatrix lane mapping: matrix id m = lane>>3
    const int lm = lane >> 3;
    const int aRowOff = ((lm & 1) << 3) + (lane & 7);          // 0..15
    const uint32_t aColB = (uint32_t)((lm >> 1) << 4);         // 0 or 16
    const uint32_t aSwz  = (uint32_t)((lane & 7) << 4);        // row swizzle
    uint32_t aRowBase[4];
#pragma unroll
    for (int mi = 0; mi < 4; mi++)
        aRowBase[mi] = (uint32_t)((warpM * 64 + mi * 16 + aRowOff) * 128);

    // B fragment addressing (fp16 pair-packed, rows 512B): R11-proven mapping,
    // channel = warpN*64 + nj*8 + lr  -> col byte = warpN*256 + nj*32 + lr*4
    const uint32_t xc = (uint32_t)(warpN * 256 + lr * 4);
    const uint32_t xSwzRow = (uint32_t)(lc << 5);              // (p&3)<<5

    // prologue
    issueA(0); issueA(1);
    {
        float4 e[2], o[2];
#pragma unroll
        for (int q = 0; q < 4; q++) { ldgX(0, q, e, o); stsX(0, q, e, o); }
    }

    for (int kt = 0; kt < NCH; kt++) {
        if (kt < NCH - 1) { CP_WAIT(1); } else { CP_WAIT(0); }
        __syncthreads();
        if (kt + 2 < NCH) issueA(kt + 2);

        const uint32_t aB = sb + (uint32_t)((kt % 3) * AS_BYTES);
        const uint32_t xB = xbase + (uint32_t)((kt & 1) * XS_BYTES);
        const bool more = (kt + 1 < NCH);

        float4 e[2], o[2];
#pragma unroll
        for (int kk = 0; kk < 4; kk++) {           // 4 k16-steps per chunk
            if (more) {
                if (kk > 0) stsX(kt + 1, kk - 1, e, o);
                ldgX(kt + 1, kk, e, o);
            }

            const int kb = kk * 8;                 // pair-row base
            uint32_t a[4][4], bf[8][2];
            const uint32_t aOff = ((uint32_t)(kk * 32) + aColB) ^ aSwz;
#pragma unroll
            for (int mi = 0; mi < 4; mi++)
                ldsm_x4(a[mi], aB + aRowBase[mi] + aOff);
#pragma unroll
            for (int nj = 0; nj < 8; nj++) {
                const uint32_t col = (xc + (uint32_t)(nj * 32)) ^ xSwzRow;
                bf[nj][0] = lds32(xB + (uint32_t)((kb + lc) * 512) + col);
                bf[nj][1] = lds32(xB + (uint32_t)((kb + lc + 4) * 512) + col);
            }
#pragma unroll
            for (int mi = 0; mi < 4; mi++)
#pragma unroll
                for (int nj = 0; nj < 8; nj++)
                    mma_f16(acc[mi][nj], a[mi], bf[nj]);
        }
        if (more) stsX(kt + 1, 3, e, o);
    }

    // epilogue: out1 = x - trend, out2 = trend
    const size_t NTOT = (size_t)BB * TT * CC;
#pragma unroll
    for (int mi = 0; mi < 4; mi++) {
#pragma unroll
        for (int half = 0; half < 2; half++) {
            const int t = t0 + warpM * 64 + mi * 16 + lr + half * 8;
            if (t >= TT) continue;
            const size_t rowb = ((size_t)b * TT + t) * CC + c0
                              + warpN * 64 + 2 * lc;
#pragma unroll
            for (int nj = 0; nj < 8; nj++) {
                const size_t o2 = rowb + nj * 8;
                const float2 xv = *(const float2*)(x + o2);
                float2 tr;
                tr.x = acc[mi][nj][2 * half + 0];
                tr.y = acc[mi][nj][2 * half + 1];
                *(float2*)(out + o2) = make_float2(xv.x - tr.x, xv.y - tr.y);
                *(float2*)(out + NTOT + o2) = tr;
            }
        }
    }
}

// ---------------------------------------------------------------------------
// Host: compose the STL trend operator A (float64), round to fp16 pair-packed.
// ---------------------------------------------------------------------------
static double h_MS[34 * NSUB];
static double h_MLP[(size_t)TT * TT];
static double h_MT[(size_t)TT * TT];
static double h_K1[(size_t)TT * TE];
static double h_S[(size_t)TT * TT];
static double h_G[(size_t)TT * TT];
static double h_T1[(size_t)TT * TT];
static double h_A[(size_t)TT * TT];
static uint32_t h_A16[(size_t)TT * KP];   // 480 rows only (pads live on device)

static void loess_mat(int n, int q, int t_lo, int nts, double* M)
{
    int qq = q < n ? q : n;
    memset(M, 0, sizeof(double) * (size_t)nts * n);
    for (int i = 0; i < nts; i++) {
        int t = t_lo + i;
        int left = t - (q - 1) / 2;
        if (left < 0) left = 0;
        if (left > n - qq) left = n - qq;
        int right = left + qq - 1;
        double h = (double)std::max(t - left, right - t);
        if (q > n) h += (q - n) / 2.0;
        double w[64], wsum = 0.0;
        for (int j = 0; j < qq; j++) {
            double u = std::fabs((double)(left + j - t)) / h;
            double c = 1.0 - u * u * u;
            if (c < 0.0) c = 0.0;
            w[j] = c * c * c;
            wsum += w[j];
        }
        for (int j = 0; j < qq; j++) w[j] /= wsum;
        double xbar = 0.0;
        for (int j = 0; j < qq; j++) xbar += w[j] * (double)(left + j);
        double var = 0.0;
        for (int j = 0; j < qq; j++) {
            double d = (double)(left + j) - xbar;
            var += w[j] * d * d;
        }
        for (int j = 0; j < qq; j++) {
            double a = w[j];
            if (var > 1e-12)
                a = w[j] * (1.0 + ((double)t - xbar) * ((double)(left + j) - xbar) / var);
            M[(size_t)i * n + left + j] = (double)(float)a;
        }
    }
}

static void mm480(const double* __restrict__ X, const double* __restrict__ Y,
                  double* __restrict__ Z)
{
    for (int i = 0; i < TT; i++) {
        double* Zi = Z + (size_t)i * TT;
        for (int j = 0; j < TT; j++) Zi[j] = 0.0;
        const double* Xi = X + (size_t)i * TT;
        for (int k = 0; k < TT; k++) {
            double a = Xi[k];
            if (a == 0.0) continue;
            const double* Yk = Y + (size_t)k * TT;
            for (int j = 0; j < TT; j++) Zi[j] += a * Yk[j];
        }
    }
}

// float -> fp16 bits, round-to-nearest-even
static uint16_t f32_to_f16(float f)
{
    uint32_t u;
    memcpy(&u, &f, 4);
    uint32_t sign = (u >> 16) & 0x8000u;
    int32_t  exp  = (int32_t)((u >> 23) & 0xFF) - 127 + 15;
    uint32_t man  = u & 0x7FFFFFu;
    if (((u >> 23) & 0xFF) == 0) return (uint16_t)sign;
    if (exp >= 31) return (uint16_t)(sign | 0x7BFFu);
    if (exp <= 0) {
        int shift = 14 - exp;
        if (shift > 24) return (uint16_t)sign;
        uint32_t mt = man | 0x800000u;
        uint32_t base = mt >> shift;
        uint32_t rem = mt & ((1u << shift) - 1u);
        uint32_t halfv = 1u << (shift - 1);
        if (rem > halfv || (rem == halfv && (base & 1u))) base++;
        return (uint16_t)(sign | base);
    }
    uint32_t base = ((uint32_t)exp << 10) + (man >> 13);
    uint32_t rem = man & 0x1FFFu;
    if (rem > 0x1000u || (rem == 0x1000u && (base & 1u))) base++;
    return (uint16_t)(sign | base);
}

static void build_operator()
{
    loess_mat(NSUB, 7,  -1, 34, h_MS);
    loess_mat(TT,   17,  0, TT, h_MLP);
    loess_mat(TT,   29,  0, TT, h_MT);

    double w31[31];
    for (int d = 0; d < 31; d++) w31[d] = 0.0;
    for (int a = 0; a < 3; a++)
        for (int b = 0; b < 15; b++)
            for (int c = 0; c < 15; c++)
                w31[a + b + c] += 1.0;
    for (int d = 0; d < 31; d++) w31[d] /= 675.0;

    memset(h_K1, 0, sizeof(h_K1));
    for (int t = 0; t < TT; t++) {
        double* Kt = h_K1 + (size_t)t * TE;
        const double* Lt = h_MLP + (size_t)t * TT;
        for (int i = 0; i < TT; i++) {
            double m = Lt[i];
            if (m == 0.0) continue;
            for (int d = 0; d < 31; d++) Kt[i + d] += m * w31[d];
        }
    }
    for (size_t i = 0; i < (size_t)TT * TE; i++) h_K1[i] = -h_K1[i];
    for (int t = 0; t < TT; t++) h_K1[(size_t)t * TE + t + PP] += 1.0;

    memset(h_S, 0, sizeof(h_S));
    for (int t = 0; t < TT; t++) {
        double* St = h_S + (size_t)t * TT;
        const double* Bt = h_K1 + (size_t)t * TE;
        for (int j = 0; j < PP; j++) {
            for (int s = 0; s < 34; s++) {
                double v = Bt[s * PP + j];
                if (v == 0.0) continue;
                const double* MSs = h_MS + (size_t)s * NSUB;
                for (int n = 0; n < NSUB; n++)
                    St[n * PP + j] += v * MSs[n];
            }
        }
    }

    for (int i = 0; i < TT; i++)
        for (int j = 0; j < TT; j++)
            h_G[(size_t)i * TT + j] = (i == j ? 1.0 : 0.0) - h_S[(size_t)i * TT + j];
    mm480(h_MT, h_G, h_T1);
    for (int i = 0; i < TT; i++)
        for (int j = 0; j < TT; j++)
            h_G[(size_t)i * TT + j] = (i == j ? 1.0 : 0.0) - h_T1[(size_t)i * TT + j];
    mm480(h_S, h_G, h_A);
    for (int i = 0; i < TT; i++)
        for (int j = 0; j < TT; j++)
            h_G[(size_t)i * TT + j] = (i == j ? 1.0 : 0.0) - h_A[(size_t)i * TT + j];
    mm480(h_MT, h_G, h_A);

    // pack fp16 pairs: word(t, kp) = f16(A[t][2kp]) | f16(A[t][2kp+1]) << 16
    memset(h_A16, 0, sizeof(h_A16));
    for (int i = 0; i < TT; i++)
        for (int kp = 0; kp < TT / 2; kp++) {
            uint32_t lo = f32_to_f16((float)h_A[(size_t)i * TT + 2 * kp]);
            uint32_t hi = f32_to_f16((float)h_A[(size_t)i * TT + 2 * kp + 1]);
            h_A16[(size_t)i * KP + kp] = lo | (hi << 16);
        }
}

// Static initializer: build the operator at program load (host work only).
static const bool s_initialized = []() {
    build_operator();
    return true;
}();

// ---------------------------------------------------------------------------
// kernel_launch  (graph-capturable ops ONLY: kernel launches)
// ---------------------------------------------------------------------------
extern "C" void kernel_launch(void* const* d_in, const int* in_sizes, int n_in,
                              void* d_out, int out_size)
{
    (void)in_sizes; (void)n_in; (void)out_size;
    (void)s_initialized;

    cudaFuncSetAttribute(stl_mma_kernel,
                         cudaFuncAttributeMaxDynamicSharedMemorySize, SMEM_BYTES);

    // upload A by reading the host static directly (GB300 ATS/HMM)
    copyA_kernel<<<(TT * KP / 4) / 128, 128>>>((const uint4*)h_A16);

    const float* x = (const float*)d_in[0];
    float* out = (float*)d_out;

    dim3 grid(TPAD / BM, CC / 128, BB);   // (4, 2, 128)
    stl_mma_kernel<<<grid, 128, SMEM_BYTES>>>(x, out);
}

// round 16
// speedup vs baseline: 1.3306x; 1.3306x over previous
#include <cuda_runtime.h>
#include <cuda_fp16.h>
#include <cstdint>
#include <cmath>
#include <cstring>
#include <algorithm>

// ---------------------------------------------------------------------------
// Problem constants
// ---------------------------------------------------------------------------
#define TT   480
#define PP   15
#define NSUB 32
#define TE   510
#define CC   256
#define BB   128
#define TPAD 512
#define KP   256           // k-pairs after padding K to 512
#define NCH  8             // K chunks of 64 (=32 pairs)
#define BM   128           // CTA M tile

// SMEM: A stages fp16 pair-packed: 128 rows x 128B, swizzle (row&7)<<4, x3
//       X stages fp16 pair-packed:  32 pair-rows x 512B, swizzle (p&3)<<5, x2
#define AS_BYTES 16384
#define XS_BYTES 16384
#define SMEM_BYTES (3 * AS_BYTES + 2 * XS_BYTES)   // 81920 -> 2 CTAs/SM

__device__ uint32_t g_A16[TPAD * KP];   // fp16 pair-packed operator (pad rows
                                        // 480..511 stay zero from module init)

// ---------------------------------------------------------------------------
// PTX helpers (sm_80-portable)
// ---------------------------------------------------------------------------
__device__ __forceinline__ uint32_t smem_u32(const void* p) {
    uint32_t a;
    asm("{ .reg .u64 t; cvta.to.shared.u64 t, %1; cvt.u32.u64 %0, t; }"
        : "=r"(a) : "l"(p));
    return a;
}
__device__ __forceinline__ void cp16(uint32_t dst, const void* src) {
    asm volatile("cp.async.cg.shared.global [%0], [%1], 16;" :: "r"(dst), "l"(src));
}
#define CP_COMMIT() asm volatile("cp.async.commit_group;" ::: "memory")
#define CP_WAIT(n)  asm volatile("cp.async.wait_group %0;" :: "n"(n) : "memory")

__device__ __forceinline__ void ldsm_x4(uint32_t* r, uint32_t addr) {
    asm volatile(
        "ldmatrix.sync.aligned.m8n8.x4.shared.b16 {%0,%1,%2,%3}, [%4];"
        : "=r"(r[0]), "=r"(r[1]), "=r"(r[2]), "=r"(r[3]) : "r"(addr));
}
__device__ __forceinline__ uint32_t lds32(uint32_t addr) {
    uint32_t v;
    asm volatile("ld.shared.b32 %0, [%1];" : "=r"(v) : "r"(addr));
    return v;
}
__device__ __forceinline__ void sts128(uint32_t addr, uint32_t w0, uint32_t w1,
                                       uint32_t w2, uint32_t w3) {
    asm volatile("st.shared.v4.b32 [%0], {%1,%2,%3,%4};"
                 :: "r"(addr), "r"(w0), "r"(w1), "r"(w2), "r"(w3) : "memory");
}
// pack two f32 -> f16x2 word; lo half = e (even k), hi half = o (odd k)
__device__ __forceinline__ uint32_t cvt_f16x2(float o, float e) {
    uint32_t w;
    asm("cvt.rn.f16x2.f32 %0, %1, %2;" : "=r"(w) : "f"(o), "f"(e));
    return w;
}

// fp16 MMA: D(f32) += A(f16) * B(f16), m16n8k16
__device__ __forceinline__ void mma_f16(float* d, const uint32_t* a,
                                        const uint32_t* b) {
    asm volatile(
        "mma.sync.aligned.m16n8k16.row.col.f32.f16.f16.f32 "
        "{%0,%1,%2,%3}, {%4,%5,%6,%7}, {%8,%9}, {%0,%1,%2,%3};"
        : "+f"(d[0]), "+f"(d[1]), "+f"(d[2]), "+f"(d[3])
        : "r"(a[0]), "r"(a[1]), "r"(a[2]), "r"(a[3]),
          "r"(b[0]), "r"(b[1]));
}

// ---------------------------------------------------------------------------
// Operator upload: read the HOST static h_A16 directly via ATS (GB300 is
// HMM-coherent; system-memory LDG works without pinning) and store to g_A16.
// 480*256 words = 30720 uint4. Validated in R15 (overhead 18 -> 10.5 us).
// ---------------------------------------------------------------------------
__global__ void __launch_bounds__(128) copyA_kernel(const uint4* __restrict__ src)
{
    const int i = blockIdx.x * 128 + threadIdx.x;
    ((uint4*)g_A16)[i] = src[i];
}

// ---------------------------------------------------------------------------
// GEMM: per CTA: batch b, 128 t-rows (A padded to 512), 128 channels.
// trend = A @ x ; out[0..N) = x - trend ; out[N..2N) = trend
// 256 threads = 8 warps in 2(M) x 4(N); warp tile 64x32; BK=64;
// A fp16 cp.async 3-stage (prefetch-2).
// X: fused LDG(fp32) -> cvt -> STS(fp16 pair-packed), 2-stage, staged in regs
//    half-chunk at a time (16 regs) and interleaved with the MMA steps.
// (R14 configuration: measured 82.4 us, 126 regs, 2 CTAs/SM.)
// ---------------------------------------------------------------------------
__global__ void __launch_bounds__(256, 2) stl_mma_kernel(
    const float* __restrict__ x, float* __restrict__ out)
{
    extern __shared__ __align__(16) char smem[];
    const uint32_t sb = smem_u32(smem);
    const uint32_t xbase = sb + 3 * AS_BYTES;

    const int tid = threadIdx.x;
    const int lane = tid & 31, wid = tid >> 5;
    const int warpM = wid & 1, warpN = wid >> 1;
    const int t0 = blockIdx.x * BM;
    const int c0 = blockIdx.y * 128;
    const int b  = blockIdx.z;

    const uint32_t* gAr = g_A16 + (size_t)t0 * KP;         // [t][pair]
    const float*    gXr = x + (size_t)b * TT * CC + c0;    // [k][c] fp32

    // A loader indices
    const int la_r = tid >> 3;                  // rows la_r + i*32, i<4
    const uint32_t la_c16 = (tid & 7) * 16;     // 16B unit within 128B row

    auto issueA = [&](int kt) {
        const uint32_t aB = sb + (uint32_t)((kt % 3) * AS_BYTES);
        const int p0 = kt * 32;                 // pair offset
#pragma unroll
        for (int i = 0; i < 4; i++) {
            const int r = la_r + i * 32;
            cp16(aB + (uint32_t)r * 128 + (la_c16 ^ (uint32_t)((r & 7) << 4)),
                 gAr + (size_t)r * KP + p0 + (tid & 7) * 4);
        }
        CP_COMMIT();
    };

    // X loader: half h of chunk kt -> 2 units/thread; unit covers one 16B
    // pair-word group: pairs p, channels c..c+3.
    auto ldgX = [&](int kt, int h, float4* e, float4* o) {
#pragma unroll
        for (int u = 0; u < 2; u++) {
            const int id = tid + u * 256;
            const int p = kt * 32 + h * 16 + (id >> 5);    // global pair
            const int c = (id & 31) * 4;
            if (p < TT / 2) {
                e[u] = *(const float4*)(gXr + (size_t)(2 * p) * CC + c);
                o[u] = *(const float4*)(gXr + (size_t)(2 * p + 1) * CC + c);
            } else {
                e[u] = make_float4(0.f, 0.f, 0.f, 0.f);
                o[u] = make_float4(0.f, 0.f, 0.f, 0.f);
            }
        }
    };
    auto stsX = [&](int kt, int h, const float4* e, const float4* o) {
        const uint32_t xB = xbase + (uint32_t)((kt & 1) * XS_BYTES);
#pragma unroll
        for (int u = 0; u < 2; u++) {
            const int id = tid + u * 256;
            const int pl = h * 16 + (id >> 5);             // local pair row
            const uint32_t c16 = (uint32_t)(id & 31) * 16;
            const uint32_t addr = xB + (uint32_t)pl * 512 +
                                  (c16 ^ (uint32_t)((pl & 3) << 5));
            sts128(addr,
                   cvt_f16x2(o[u].x, e[u].x), cvt_f16x2(o[u].y, e[u].y),
                   cvt_f16x2(o[u].z, e[u].z), cvt_f16x2(o[u].w, e[u].w));
        }
    };

    float acc[4][4][4];
#pragma unroll
    for (int mi = 0; mi < 4; mi++)
#pragma unroll
        for (int nj = 0; nj < 4; nj++)
#pragma unroll
            for (int r = 0; r < 4; r++) acc[mi][nj][r] = 0.0f;

    const int lr = lane >> 2, lc = lane & 3;

    // ldmatrix lane mapping: matrix id m = lane>>3
    const int lm = lane >> 3;
    const int aRowOff = ((lm & 1) << 3) + (lane & 7);          // 0..15
    const uint32_t aColB = (uint32_t)((lm >> 1) << 4);         // 0 or 16
    const uint32_t aSwz  = (uint32_t)((lane & 7) << 4);        // row swizzle
    uint32_t aRowBase[4];
#pragma unroll
    for (int mi = 0; mi < 4; mi++)
        aRowBase[mi] = (uint32_t)((warpM * 64 + mi * 16 + aRowOff) * 128);

    // B fragment addressing (fp16 pair-packed, rows 512B): R11-proven
    const uint32_t xc = (uint32_t)(warpN * 128 + lr * 4);      // col byte base
    const uint32_t xSwzRow = (uint32_t)(lc << 5);              // (p&3)<<5

    // prologue
    issueA(0); issueA(1);
    {
        float4 e[2], o[2];
        ldgX(0, 0, e, o); stsX(0, 0, e, o);
        ldgX(0, 1, e, o); stsX(0, 1, e, o);
    }

    for (int kt = 0; kt < NCH; kt++) {
        if (kt < NCH - 1) { CP_WAIT(1); } else { CP_WAIT(0); }
        __syncthreads();
        if (kt + 2 < NCH) issueA(kt + 2);

        const uint32_t aB = sb + (uint32_t)((kt % 3) * AS_BYTES);
        const uint32_t xB = xbase + (uint32_t)((kt & 1) * XS_BYTES);
        const bool more = (kt + 1 < NCH);

        float4 e[2], o[2];
#pragma unroll
        for (int kk = 0; kk < 4; kk++) {           // 4 k16-steps per chunk
            if (kk == 0 && more) ldgX(kt + 1, 0, e, o);
            if (kk == 2 && more) { stsX(kt + 1, 0, e, o); ldgX(kt + 1, 1, e, o); }

            const int kb = kk * 8;                 // pair-row base
            uint32_t a[4][4], bf[4][2];
            const uint32_t aOff = ((uint32_t)(kk * 32) + aColB) ^ aSwz;
#pragma unroll
            for (int mi = 0; mi < 4; mi++)
                ldsm_x4(a[mi], aB + aRowBase[mi] + aOff);
#pragma unroll
            for (int nj = 0; nj < 4; nj++) {
                const uint32_t col = (xc + (uint32_t)(nj * 32)) ^ xSwzRow;
                bf[nj][0] = lds32(xB + (uint32_t)((kb + lc) * 512) + col);
                bf[nj][1] = lds32(xB + (uint32_t)((kb + lc + 4) * 512) + col);
            }
#pragma unroll
            for (int mi = 0; mi < 4; mi++)
#pragma unroll
                for (int nj = 0; nj < 4; nj++)
                    mma_f16(acc[mi][nj], a[mi], bf[nj]);
        }
        if (more) stsX(kt + 1, 1, e, o);
    }

    // epilogue: out1 = x - trend, out2 = trend
    const size_t NTOT = (size_t)BB * TT * CC;
#pragma unroll
    for (int mi = 0; mi < 4; mi++) {
#pragma unroll
        for (int half = 0; half < 2; half++) {
            const int t = t0 + warpM * 64 + mi * 16 + lr + half * 8;
            if (t >= TT) continue;
            const size_t rowb = ((size_t)b * TT + t) * CC + c0
                              + warpN * 32 + 2 * lc;
#pragma unroll
            for (int nj = 0; nj < 4; nj++) {
                const size_t o2 = rowb + nj * 8;
                const float2 xv = *(const float2*)(x + o2);
                float2 tr;
                tr.x = acc[mi][nj][2 * half + 0];
                tr.y = acc[mi][nj][2 * half + 1];
                *(float2*)(out + o2) = make_float2(xv.x - tr.x, xv.y - tr.y);
                *(float2*)(out + NTOT + o2) = tr;
            }
        }
    }
}

// ---------------------------------------------------------------------------
// Host: compose the STL trend operator A (float64), round to fp16 pair-packed.
// ---------------------------------------------------------------------------
static double h_MS[34 * NSUB];
static double h_MLP[(size_t)TT * TT];
static double h_MT[(size_t)TT * TT];
static double h_K1[(size_t)TT * TE];
static double h_S[(size_t)TT * TT];
static double h_G[(size_t)TT * TT];
static double h_T1[(size_t)TT * TT];
static double h_A[(size_t)TT * TT];
static uint32_t h_A16[(size_t)TT * KP];   // 480 rows only (pads live on device)

static void loess_mat(int n, int q, int t_lo, int nts, double* M)
{
    int qq = q < n ? q : n;
    memset(M, 0, sizeof(double) * (size_t)nts * n);
    for (int i = 0; i < nts; i++) {
        int t = t_lo + i;
        int left = t - (q - 1) / 2;
        if (left < 0) left = 0;
        if (left > n - qq) left = n - qq;
        int right = left + qq - 1;
        double h = (double)std::max(t - left, right - t);
        if (q > n) h += (q - n) / 2.0;
        double w[64], wsum = 0.0;
        for (int j = 0; j < qq; j++) {
            double u = std::fabs((double)(left + j - t)) / h;
            double c = 1.0 - u * u * u;
            if (c < 0.0) c = 0.0;
            w[j] = c * c * c;
            wsum += w[j];
        }
        for (int j = 0; j < qq; j++) w[j] /= wsum;
        double xbar = 0.0;
        for (int j = 0; j < qq; j++) xbar += w[j] * (double)(left + j);
        double var = 0.0;
        for (int j = 0; j < qq; j++) {
            double d = (double)(left + j) - xbar;
            var += w[j] * d * d;
        }
        for (int j = 0; j < qq; j++) {
            double a = w[j];
            if (var > 1e-12)
                a = w[j] * (1.0 + ((double)t - xbar) * ((double)(left + j) - xbar) / var);
            M[(size_t)i * n + left + j] = (double)(float)a;
        }
    }
}

static void mm480(const double* __restrict__ X, const double* __restrict__ Y,
                  double* __restrict__ Z)
{
    for (int i = 0; i < TT; i++) {
        double* Zi = Z + (size_t)i * TT;
        for (int j = 0; j < TT; j++) Zi[j] = 0.0;
        const double* Xi = X + (size_t)i * TT;
        for (int k = 0; k < TT; k++) {
            double a = Xi[k];
            if (a == 0.0) continue;
            const double* Yk = Y + (size_t)k * TT;
            for (int j = 0; j < TT; j++) Zi[j] += a * Yk[j];
        }
    }
}

// float -> fp16 bits, round-to-nearest-even
static uint16_t f32_to_f16(float f)
{
    uint32_t u;
    memcpy(&u, &f, 4);
    uint32_t sign = (u >> 16) & 0x8000u;
    int32_t  exp  = (int32_t)((u >> 23) & 0xFF) - 127 + 15;
    uint32_t man  = u & 0x7FFFFFu;
    if (((u >> 23) & 0xFF) == 0) return (uint16_t)sign;
    if (exp >= 31) return (uint16_t)(sign | 0x7BFFu);
    if (exp <= 0) {
        int shift = 14 - exp;
        if (shift > 24) return (uint16_t)sign;
        uint32_t mt = man | 0x800000u;
        uint32_t base = mt >> shift;
        uint32_t rem = mt & ((1u << shift) - 1u);
        uint32_t halfv = 1u << (shift - 1);
        if (rem > halfv || (rem == halfv && (base & 1u))) base++;
        return (uint16_t)(sign | base);
    }
    uint32_t base = ((uint32_t)exp << 10) + (man >> 13);
    uint32_t rem = man & 0x1FFFu;
    if (rem > 0x1000u || (rem == 0x1000u && (base & 1u))) base++;
    return (uint16_t)(sign | base);
}

static void build_operator()
{
    loess_mat(NSUB, 7,  -1, 34, h_MS);
    loess_mat(TT,   17,  0, TT, h_MLP);
    loess_mat(TT,   29,  0, TT, h_MT);

    double w31[31];
    for (int d = 0; d < 31; d++) w31[d] = 0.0;
    for (int a = 0; a < 3; a++)
        for (int b = 0; b < 15; b++)
            for (int c = 0; c < 15; c++)
                w31[a + b + c] += 1.0;
    for (int d = 0; d < 31; d++) w31[d] /= 675.0;

    memset(h_K1, 0, sizeof(h_K1));
    for (int t = 0; t < TT; t++) {
        double* Kt = h_K1 + (size_t)t * TE;
        const double* Lt = h_MLP + (size_t)t * TT;
        for (int i = 0; i < TT; i++) {
            double m = Lt[i];
            if (m == 0.0) continue;
            for (int d = 0; d < 31; d++) Kt[i + d] += m * w31[d];
        }
    }
    for (size_t i = 0; i < (size_t)TT * TE; i++) h_K1[i] = -h_K1[i];
    for (int t = 0; t < TT; t++) h_K1[(size_t)t * TE + t + PP] += 1.0;

    memset(h_S, 0, sizeof(h_S));
    for (int t = 0; t < TT; t++) {
        double* St = h_S + (size_t)t * TT;
        const double* Bt = h_K1 + (size_t)t * TE;
        for (int j = 0; j < PP; j++) {
            for (int s = 0; s < 34; s++) {
                double v = Bt[s * PP + j];
                if (v == 0.0) continue;
                const double* MSs = h_MS + (size_t)s * NSUB;
                for (int n = 0; n < NSUB; n++)
                    St[n * PP + j] += v * MSs[n];
            }
        }
    }

    for (int i = 0; i < TT; i++)
        for (int j = 0; j < TT; j++)
            h_G[(size_t)i * TT + j] = (i == j ? 1.0 : 0.0) - h_S[(size_t)i * TT + j];
    mm480(h_MT, h_G, h_T1);
    for (int i = 0; i < TT; i++)
        for (int j = 0; j < TT; j++)
            h_G[(size_t)i * TT + j] = (i == j ? 1.0 : 0.0) - h_T1[(size_t)i * TT + j];
    mm480(h_S, h_G, h_A);
    for (int i = 0; i < TT; i++)
        for (int j = 0; j < TT; j++)
            h_G[(size_t)i * TT + j] = (i == j ? 1.0 : 0.0) - h_A[(size_t)i * TT + j];
    mm480(h_MT, h_G, h_A);

    // pack fp16 pairs: word(t, kp) = f16(A[t][2kp]) | f16(A[t][2kp+1]) << 16
    memset(h_A16, 0, sizeof(h_A16));
    for (int i = 0; i < TT; i++)
        for (int kp = 0; kp < TT / 2; kp++) {
            uint32_t lo = f32_to_f16((float)h_A[(size_t)i * TT + 2 * kp]);
            uint32_t hi = f32_to_f16((float)h_A[(size_t)i * TT + 2 * kp + 1]);
            h_A16[(size_t)i * KP + kp] = lo | (hi << 16);
        }
}

// Static initializer: build the operator at program load (host work only).
static const bool s_initialized = []() {
    build_operator();
    return true;
}();

// ---------------------------------------------------------------------------
// kernel_launch  (graph-capturable ops ONLY: kernel launches)
// ---------------------------------------------------------------------------
extern "C" void kernel_launch(void* const* d_in, const int* in_sizes, int n_in,
                              void* d_out, int out_size)
{
    (void)in_sizes; (void)n_in; (void)out_size;
    (void)s_initialized;

    cudaFuncSetAttribute(stl_mma_kernel,
                         cudaFuncAttributeMaxDynamicSharedMemorySize, SMEM_BYTES);

    // upload A by reading the host static directly (GB300 ATS/HMM)
    copyA_kernel<<<(TT * KP / 4) / 128, 128>>>((const uint4*)h_A16);

    const float* x = (const float*)d_in[0];
    float* out = (float*)d_out;

    dim3 grid(TPAD / BM, CC / 128, BB);   // (4, 2, 128)
    stl_mma_kernel<<<grid, 256, SMEM_BYTES>>>(x, out);
}